// round 13
// baseline (speedup 1.0000x reference)
#include <cuda_runtime.h>
#include <cuda_fp16.h>
#include <cstdint>

// ============================================================
// Problem: out[B,256] = relu(X[B,1024] @ W^T + c)
//   X = [text | image], W/c precomputed from small weights.
//   B = 65536, H = 256, K = 1024.
// Reassociated precompute (depth 2, ONE kernel w/ device barrier):
//   Phase1: X1 = Wf1@Wo, X2 = Wf2@Wo, Y_t = Wv@W_text, Y_i = Wv@W_img,
//           b1 = Wo@bv + bo, u_t = Wv@b_text, u_i = Wv@b_img
//   Phase2: W[:, :512] = X2@Y_t ; W[:, 512:] = X1@Y_i  (fp16)
//           c = X1@u_i + X2@u_t + (Wf1+Wf2)@b1 + b_fuse
// ============================================================
#define HDIM 256
#define KTOT 1024
#define PRE_GRID 128                     // 8*4*4 CTAs, all co-resident

// ---------------- device scratch ----------------
__device__ float  g_X1[HDIM * HDIM];
__device__ float  g_X2[HDIM * HDIM];
__device__ float  g_Yt[HDIM * 512];
__device__ float  g_Yi[HDIM * 512];
__device__ __half g_W16[HDIM * KTOT];
__device__ float  g_b1[HDIM];
__device__ float  g_ut[HDIM];
__device__ float  g_ui[HDIM];
__device__ float  g_c[HDIM];
// spin-barrier state (replay-safe: crosswise resets)
__device__ int g_barA = 0;
__device__ int g_rel  = 0;
__device__ int g_barB = 0;

// ---------------- PTX helpers ----------------
__device__ __forceinline__ uint32_t smem_u32(const void* p) {
    uint32_t a;
    asm("{ .reg .u64 t; cvta.to.shared.u64 t, %1; cvt.u32.u64 %0, t; }"
        : "=r"(a) : "l"(p));
    return a;
}

#define SW(x) ((x) ^ (((x) >> 3) & 0x70))

#define LDSM_X4(r0, r1, r2, r3, addr) \
    asm volatile("ldmatrix.sync.aligned.m8n8.x4.shared.b16 {%0,%1,%2,%3}, [%4];\n" \
        : "=r"(r0), "=r"(r1), "=r"(r2), "=r"(r3) : "r"(addr))

#define MMA16816(d, a, b0_, b1_) \
    asm volatile("mma.sync.aligned.m16n8k16.row.col.f32.f16.f16.f32 " \
        "{%0,%1,%2,%3}, {%4,%5,%6,%7}, {%8,%9}, {%0,%1,%2,%3};\n" \
        : "+f"((d)[0]), "+f"((d)[1]), "+f"((d)[2]), "+f"((d)[3]) \
        : "r"((a)[0]), "r"((a)[1]), "r"((a)[2]), "r"((a)[3]), "r"(b0_), "r"(b1_))

#define CP_ASYNC16(dst, src) \
    asm volatile("cp.async.cg.shared.global [%0], [%1], 16;\n" :: "r"(dst), "l"(src))
#define CP_COMMIT() asm volatile("cp.async.commit_group;\n")
#define CP_WAIT0()  asm volatile("cp.async.wait_group 0;\n" ::: "memory")

// ============================================================
// Precompute GEMM body: 64x64 tile, 512 threads, intra-CTA split-K,
// smem passed in (dynamic) so two instantiations share one buffer.
// ============================================================
template<bool HALF_OUT>
__device__ __forceinline__ void gemm64_body2(float* __restrict__ Asm,
                                             float* __restrict__ Bsm,
                                             const float* __restrict__ A, int lda,
                                             const float* __restrict__ B, int ldb,
                                             void* __restrict__ C, int ldc, int K,
                                             int i0, int j0) {
    // Asm/Bsm layout: [h][32][72] -> ((h*32)+k)*72 + col
    const int t  = threadIdx.x;        // 0..511
    const int h  = t >> 8;             // K-half (0 or 1)
    const int lt = t & 255;
    const int tx = lt & 15, ty = lt >> 4;
    const int khalf = K >> 1;
    const int kbase = h * khalf;
    float* As = Asm + h * 32 * 72;
    float* Bs = Bsm + h * 32 * 72;
    float acc[4][4] = {};

    int ar[8], ac[8], br[8], bc[8];
    #pragma unroll
    for (int u = 0; u < 8; u++) {
        int idx = lt + u * 256;
        ar[u] = idx >> 5;  ac[u] = idx & 31;   // A: 64 rows x 32 k
        br[u] = idx >> 6;  bc[u] = idx & 63;   // B: 32 k x 64 cols
    }
    float ra[8], rb[8];
    #pragma unroll
    for (int u = 0; u < 8; u++) {
        ra[u] = A[(size_t)(i0 + ar[u]) * lda + kbase + ac[u]];
        rb[u] = B[(size_t)(kbase + br[u]) * ldb + j0 + bc[u]];
    }

    for (int k0 = kbase; k0 < kbase + khalf; k0 += 32) {
        #pragma unroll
        for (int u = 0; u < 8; u++) {
            As[ac[u] * 72 + ar[u]] = ra[u];
            Bs[br[u] * 72 + bc[u]] = rb[u];
        }
        __syncthreads();
        if (k0 + 32 < kbase + khalf) {
            #pragma unroll
            for (int u = 0; u < 8; u++) {
                ra[u] = A[(size_t)(i0 + ar[u]) * lda + k0 + 32 + ac[u]];
                rb[u] = B[(size_t)(k0 + 32 + br[u]) * ldb + j0 + bc[u]];
            }
        }
        #pragma unroll
        for (int k = 0; k < 32; k++) {
            float4 a4 = *(const float4*)&As[k * 72 + ty * 4];
            float4 b4 = *(const float4*)&Bs[k * 72 + tx * 4];
            acc[0][0] += a4.x * b4.x; acc[0][1] += a4.x * b4.y;
            acc[0][2] += a4.x * b4.z; acc[0][3] += a4.x * b4.w;
            acc[1][0] += a4.y * b4.x; acc[1][1] += a4.y * b4.y;
            acc[1][2] += a4.y * b4.z; acc[1][3] += a4.y * b4.w;
            acc[2][0] += a4.z * b4.x; acc[2][1] += a4.z * b4.y;
            acc[2][2] += a4.z * b4.z; acc[2][3] += a4.z * b4.w;
            acc[3][0] += a4.w * b4.x; acc[3][1] += a4.w * b4.y;
            acc[3][2] += a4.w * b4.z; acc[3][3] += a4.w * b4.w;
        }
        __syncthreads();
    }

    // ---- reduce half 1 into half 0 via smem (reuse Asm space) ----
    float* red = Asm;                  // 16 x 257 floats fits in Asm (4608)
    if (h == 1) {
        #pragma unroll
        for (int i = 0; i < 16; i++)
            red[i * 257 + lt] = acc[i >> 2][i & 3];
    }
    __syncthreads();
    if (h == 0) {
        #pragma unroll
        for (int i = 0; i < 16; i++)
            acc[i >> 2][i & 3] += red[i * 257 + lt];
        #pragma unroll
        for (int r = 0; r < 4; r++)
            #pragma unroll
            for (int c = 0; c < 4; c++) {
                size_t o = (size_t)(i0 + ty * 4 + r) * ldc + j0 + tx * 4 + c;
                if (HALF_OUT) ((__half*)C)[o] = __float2half_rn(acc[r][c]);
                else          ((float*)C)[o]  = acc[r][c];
            }
    }
    __syncthreads();   // protect smem reuse by caller's next call
}

__device__ __forceinline__ float dot256(const float* __restrict__ a,
                                        const float* __restrict__ b) {
    const float4* a4 = (const float4*)a;
    const float4* b4 = (const float4*)b;
    float s = 0.f;
    #pragma unroll 8
    for (int k = 0; k < 64; k++) {
        float4 x = __ldg(&a4[k]), y = __ldg(&b4[k]);
        s += x.x * y.x + x.y * y.y + x.z * y.z + x.w * y.w;
    }
    return s;
}

// ============================================================
// Merged precompute: ONE kernel, grid (8,4,4) = 128 CTAs (all
// co-resident), 512 threads, device-wide spin barrier between
// the two dependency phases. Replay-safe counter resets.
// ============================================================
#define PRE_SMEM (2 * 32 * 72 * 4 * 2)   // As+Bs, 2 K-halves: 36864 B

__global__ void __launch_bounds__(512, 1)
k_pre(const float* __restrict__ Wo, const float* __restrict__ Wv,
      const float* __restrict__ W_fuse,
      const float* __restrict__ W_text, const float* __restrict__ W_img,
      const float* __restrict__ in_proj_b,
      const float* __restrict__ out_proj_b,
      const float* __restrict__ b_text, const float* __restrict__ b_img,
      const float* __restrict__ b_fuse) {
    extern __shared__ float psm[];
    float* Asm = psm;
    float* Bsm = psm + 2 * 32 * 72;
    const int z = blockIdx.z;

    // ---------------- phase 1 (input-only work) ----------------
    if (z == 0) {
        if (blockIdx.x < 4) {
            gemm64_body2<false>(Asm, Bsm, W_fuse, 512, Wo, 256, g_X1, 256, 256,
                                blockIdx.y * 64, blockIdx.x * 64);
        } else if (blockIdx.y == 0 && threadIdx.x < 256) {
            const int i = threadIdx.x;
            if (blockIdx.x == 4)
                g_b1[i] = dot256(Wo + i * HDIM, in_proj_b + 2 * HDIM) + out_proj_b[i];
            else if (blockIdx.x == 5)
                g_ut[i] = dot256(Wv + i * HDIM, b_text);
            else if (blockIdx.x == 6)
                g_ui[i] = dot256(Wv + i * HDIM, b_img);
        }
    } else if (z == 1) {
        if (blockIdx.x < 4)
            gemm64_body2<false>(Asm, Bsm, W_fuse + 256, 512, Wo, 256, g_X2, 256, 256,
                                blockIdx.y * 64, blockIdx.x * 64);
    } else if (z == 2) {
        gemm64_body2<false>(Asm, Bsm, Wv, 256, W_text, 512, g_Yt, 512, 256,
                            blockIdx.y * 64, blockIdx.x * 64);
    } else {
        gemm64_body2<false>(Asm, Bsm, Wv, 256, W_img, 512, g_Yi, 512, 256,
                            blockIdx.y * 64, blockIdx.x * 64);
    }

    // ---------------- device-wide barrier ----------------
    __threadfence();
    __syncthreads();
    if (threadIdx.x == 0) {
        int v = atomicAdd(&g_barA, 1);
        if (v == PRE_GRID - 1) {
            g_barB = 0;                 // reset barrier-2 state BEFORE release
            __threadfence();
            atomicExch(&g_rel, 1);      // release
        }
        while (*(volatile int*)&g_rel == 0) {}
    }
    __syncthreads();
    __threadfence();

    // ---------------- phase 2 ----------------
    if (z == 0) {
        gemm64_body2<true>(Asm, Bsm, g_X2, 256, g_Yt, 512, g_W16, 1024, 256,
                           blockIdx.y * 64, blockIdx.x * 64);
    } else if (z == 1) {
        gemm64_body2<true>(Asm, Bsm, g_X1, 256, g_Yi, 512, g_W16 + 512, 1024, 256,
                           blockIdx.y * 64, blockIdx.x * 64);
    } else if (z == 2 && blockIdx.x == 0 && blockIdx.y == 0 && threadIdx.x < 256) {
        const int i = threadIdx.x;
        float s = b_fuse[i] + dot256(g_X1 + i * HDIM, g_ui)
                            + dot256(g_X2 + i * HDIM, g_ut);
        const float4* w1 = (const float4*)(W_fuse + i * 512);
        const float4* w2 = (const float4*)(W_fuse + i * 512 + 256);
        const float4* v1 = (const float4*)g_b1;
        #pragma unroll 8
        for (int k = 0; k < 64; k++) {
            float4 c1 = __ldg(&w1[k]), c2 = __ldg(&w2[k]), b = v1[k];
            s += (c1.x + c2.x) * b.x + (c1.y + c2.y) * b.y
               + (c1.z + c2.z) * b.z + (c1.w + c2.w) * b.w;
        }
        g_c[i] = s;
    }

    // ---------------- barrier 2: reset barrier-1 state for next replay ----
    __threadfence();
    __syncthreads();
    if (threadIdx.x == 0) {
        int v = atomicAdd(&g_barB, 1);
        if (v == PRE_GRID - 1) {
            g_barA = 0;
            g_rel  = 0;
            __threadfence();
        }
    }
}

// ============================================================
// Main GEMM (EXACT round-9/12 structure, best measured):
// CTA tile 64x256, 256 threads (8 warps, warp 32x64), K-chunk 64,
// double-buffered smem, 2 CTAs/SM, reg-prefetched A, cp.async B,
// constant-index fragment pipelining.
// ============================================================
#define STAGE 40960                    // 8KB A + 32KB B
#define DYNSMEM (1024 + 1024 + 2 * STAGE)

__global__ void __launch_bounds__(256, 2)
fused_gemm(const float* __restrict__ text, const float* __restrict__ image,
           float* __restrict__ out) {
    extern __shared__ char smem_raw[];
    char* dsm = (char*)(((uintptr_t)smem_raw + 1023) & ~(uintptr_t)1023);
    const uint32_t sb = smem_u32(dsm);
    const int tid = threadIdx.x;
    const int lane = tid & 31;
    const int wid = tid >> 5;          // 0..7
    const int wm = wid & 1;            // 2 m-blocks of 32
    const int wn = wid >> 1;           // 4 n-blocks of 64
    const int mblk = blockIdx.x;

    float* bias_s = (float*)dsm;
    bias_s[tid] = g_c[tid];

    const float* srcT = text  + (size_t)mblk * 64 * 512;
    const float* srcI = image + (size_t)mblk * 64 * 512;

    const int a_c4 = tid & 15, a_r0 = tid >> 4;   // A: rows a_r0 + u*16, u<4
    const int b_c16 = tid & 7, b_r0 = tid >> 3;   // B: rows b_r0 + u*32, u<8

    // -------- prologue: chunk 0 --------
    float4 fa[4];
    #pragma unroll
    for (int u = 0; u < 4; u++)
        fa[u] = __ldg((const float4*)(srcT + (size_t)(a_r0 + u * 16) * 512 + a_c4 * 4));
    {
        uint32_t Bb = sb + 1024 + 8192;
        #pragma unroll
        for (int u = 0; u < 8; u++) {
            int r = b_r0 + u * 32;
            uint32_t dst = Bb + SW((uint32_t)(r * 128 + b_c16 * 16));
            CP_ASYNC16(dst, g_W16 + (size_t)r * 1024 + b_c16 * 8);
        }
        CP_COMMIT();
    }
    {
        char* Ab = dsm + 1024;
        #pragma unroll
        for (int u = 0; u < 4; u++) {
            int r = a_r0 + u * 16;
            uint32_t off = SW((uint32_t)(r * 128 + a_c4 * 8));
            __half2 h0 = __floats2half2_rn(fa[u].x, fa[u].y);
            __half2 h1 = __floats2half2_rn(fa[u].z, fa[u].w);
            *(uint2*)(Ab + off) = make_uint2(*(uint32_t*)&h0, *(uint32_t*)&h1);
        }
    }
    CP_WAIT0();
    __syncthreads();

    float acc[2][8][4] = {};

    const uint32_t xorv  = (uint32_t)((lane & 7) << 4);
    const int      rl    = lane & 15;
    const uint32_t khalf = (uint32_t)(((lane >> 4) & 1) * 16);

    #pragma unroll 1
    for (int kc = 0; kc < 16; kc++) {
        const int cur = kc & 1;
        const int nxt = cur ^ 1;

        // ---- prefetch next chunk: A -> regs, B -> cp.async ----
        if (kc < 15) {
            const int kn = kc + 1;
            const float* src = (kn < 8) ? srcT : srcI;
            const int kl = (kn & 7) * 64;
            #pragma unroll
            for (int u = 0; u < 4; u++)
                fa[u] = __ldg((const float4*)(src + (size_t)(a_r0 + u * 16) * 512 + kl + a_c4 * 4));
            uint32_t Bb = sb + 1024 + nxt * STAGE + 8192;
            #pragma unroll
            for (int u = 0; u < 8; u++) {
                int r = b_r0 + u * 32;
                uint32_t dst = Bb + SW((uint32_t)(r * 128 + b_c16 * 16));
                CP_ASYNC16(dst, g_W16 + (size_t)r * 1024 + kn * 64 + b_c16 * 8);
            }
            CP_COMMIT();
        }

        // ---- compute on cur, fragment-pipelined ----
        const uint32_t Ab = sb + 1024 + cur * STAGE;
        const uint32_t Bb = Ab + 8192;
        uint32_t af[2][2][4];   // [ks&1][im][reg]
        uint32_t bf[2][4];      // [group&1][reg]

        // preload ks=0: A frags (both im) + B group 0
        #pragma unroll
        for (int im = 0; im < 2; im++) {
            uint32_t addr = (Ab + (uint32_t)((wm * 32 + im * 16 + rl) * 128) + khalf) ^ xorv;
            LDSM_X4(af[0][im][0], af[0][im][1], af[0][im][2], af[0][im][3], addr);
        }
        {
            uint32_t addr = (Bb + (uint32_t)((wn * 64 + rl) * 128) + khalf) ^ xorv;
            LDSM_X4(bf[0][0], bf[0][1], bf[0][2], bf[0][3], addr);
        }

        #pragma unroll
        for (int ks = 0; ks < 4; ks++) {
            const int cb = ks & 1;
            #pragma unroll
            for (int in_ = 0; in_ < 4; in_++) {
                const int bc = in_ & 1, bn = bc ^ 1;
                if (in_ < 3) {
                    // prefetch next B group within this ks
                    uint32_t addr = (Bb + (uint32_t)((wn * 64 + (in_ + 1) * 16 + rl) * 128)
                                        + (uint32_t)(ks * 32) + khalf) ^ xorv;
                    LDSM_X4(bf[bn][0], bf[bn][1], bf[bn][2], bf[bn][3], addr);
                } else if (ks < 3) {
                    // prefetch next ks: A frags + B group 0
                    #pragma unroll
                    for (int im = 0; im < 2; im++) {
                        uint32_t addr = (Ab + (uint32_t)((wm * 32 + im * 16 + rl) * 128)
                                            + (uint32_t)((ks + 1) * 32) + khalf) ^ xorv;
                        LDSM_X4(af[cb ^ 1][im][0], af[cb ^ 1][im][1],
                                af[cb ^ 1][im][2], af[cb ^ 1][im][3], addr);
                    }
                    uint32_t addr = (Bb + (uint32_t)((wn * 64 + rl) * 128)
                                        + (uint32_t)((ks + 1) * 32) + khalf) ^ xorv;
                    LDSM_X4(bf[bn][0], bf[bn][1], bf[bn][2], bf[bn][3], addr);
                }
                #pragma unroll
                for (int im = 0; im < 2; im++) {
                    MMA16816(acc[im][2 * in_],     af[cb][im], bf[bc][0], bf[bc][2]);
                    MMA16816(acc[im][2 * in_ + 1], af[cb][im], bf[bc][1], bf[bc][3]);
                }
            }
        }

        // ---- stage A-next into smem, then close the stage ----
        if (kc < 15) {
            char* Abn = dsm + 1024 + nxt * STAGE;
            #pragma unroll
            for (int u = 0; u < 4; u++) {
                int r = a_r0 + u * 16;
                uint32_t off = SW((uint32_t)(r * 128 + a_c4 * 8));
                __half2 h0 = __floats2half2_rn(fa[u].x, fa[u].y);
                __half2 h1 = __floats2half2_rn(fa[u].z, fa[u].w);
                *(uint2*)(Abn + off) = make_uint2(*(uint32_t*)&h0, *(uint32_t*)&h1);
            }
            CP_WAIT0();
        }
        __syncthreads();
    }

    // -------- epilogue: + bias, relu, store --------
    const int g = lane >> 2;
    const int cpair = (lane & 3) * 2;
    #pragma unroll
    for (int im = 0; im < 2; im++) {
        int m0 = mblk * 64 + wm * 32 + im * 16 + g;
        #pragma unroll
        for (int j = 0; j < 8; j++) {
            int n = wn * 64 + j * 8 + cpair;
            float bv0 = bias_s[n], bv1 = bias_s[n + 1];
            float2 v0 = make_float2(fmaxf(acc[im][j][0] + bv0, 0.f),
                                    fmaxf(acc[im][j][1] + bv1, 0.f));
            float2 v1 = make_float2(fmaxf(acc[im][j][2] + bv0, 0.f),
                                    fmaxf(acc[im][j][3] + bv1, 0.f));
            *(float2*)(out + (size_t)m0 * 256 + n)       = v0;
            *(float2*)(out + (size_t)(m0 + 8) * 256 + n) = v1;
        }
    }
}

// ============================================================
// kernel_launch
// ============================================================
extern "C" void kernel_launch(void* const* d_in, const int* in_sizes, int n_in,
                              void* d_out, int out_size) {
    const float* text       = (const float*)d_in[0];
    const float* image      = (const float*)d_in[1];
    const float* W_text     = (const float*)d_in[2];
    const float* b_text     = (const float*)d_in[3];
    const float* W_img      = (const float*)d_in[4];
    const float* b_img      = (const float*)d_in[5];
    const float* in_proj_w  = (const float*)d_in[6];
    const float* in_proj_b  = (const float*)d_in[7];
    const float* out_proj_w = (const float*)d_in[8];
    const float* out_proj_b = (const float*)d_in[9];
    const float* W_fuse     = (const float*)d_in[10];
    const float* b_fuse     = (const float*)d_in[11];
    const int batch = in_sizes[0] / 512;

    // Precompute: ONE kernel, 128 co-resident CTAs, device barrier inside.
    k_pre<<<dim3(8, 4, 4), 512, PRE_SMEM>>>(out_proj_w, in_proj_w + 512 * 256,
                                            W_fuse, W_text, W_img,
                                            in_proj_b, out_proj_b,
                                            b_text, b_img, b_fuse);

    cudaFuncSetAttribute(fused_gemm, cudaFuncAttributeMaxDynamicSharedMemorySize, DYNSMEM);
    fused_gemm<<<batch / 64, 256, DYNSMEM>>>(text, image, (float*)d_out);
}